// round 14
// baseline (speedup 1.0000x reference)
#include <cuda_runtime.h>
#include <math.h>

// Problem constants
constexpr int T  = 2048;
constexpr int B  = 64;
constexpr int H  = 128;
constexpr int G  = 512;   // 4*H gate rows
constexpr int IN = 128;

constexpr int CH     = 128;      // producer/consumer chunk (timesteps)
constexpr int NCHUNK = T / CH;   // 16
constexpr int RECC0  = 32;       // rec0 CTAs (2 batches each)
constexpr int NG     = 80;       // gemm CTAs (10 per gc)
constexpr int RECC1  = 32;       // rec1 CTAs (2 batches each)

typedef unsigned long long u64;

// ---------------------------------------------------------------------------
// Scratch (static __device__ arrays — no allocation in kernel_launch)
// ---------------------------------------------------------------------------
__device__ float g_xp0[(size_t)T * B * G];  // layer-0 input projections (+bias)
__device__ float g_xp1[(size_t)T * B * G];  // layer-1 input projections (+bias)
__device__ float g_hs[(size_t)T * B * H];   // layer-0 hidden states
__device__ float g_hT[B * H];               // final hidden of layer 1
// Per-chunk completion counters (drift-proof)
__device__ int   g_h0_done[NCHUNK];         // == RECC0 when chunk h0 published
__device__ int   g_xp1_done[NCHUNK];        // == NG when chunk xp1 published

__global__ void reset_flags() {
    for (int i = 0; i < NCHUNK; i++) { g_h0_done[i] = 0; g_xp1_done[i] = 0; }
}

// ---------------------------------------------------------------------------
// Packed fp32x2 helpers (PTX ISA 8.6+, sm_100+)
// ---------------------------------------------------------------------------
__device__ __forceinline__ u64 ffma2(u64 a, u64 b, u64 c) {
    u64 d;
    asm("fma.rn.f32x2 %0, %1, %2, %3;" : "=l"(d) : "l"(a), "l"(b), "l"(c));
    return d;
}
__device__ __forceinline__ u64 pack_dup(float a) {
    u64 d; asm("mov.b64 %0, {%1, %1};" : "=l"(d) : "f"(a)); return d;
}
__device__ __forceinline__ float2 unpack2(u64 a) {
    float2 r; asm("mov.b64 {%0, %1}, %2;" : "=f"(r.x), "=f"(r.y) : "l"(a)); return r;
}
__device__ __forceinline__ float hadd2(u64 a) {
    float2 r = unpack2(a); return r.x + r.y;
}
__device__ __forceinline__ float sigf(float x) {
    return __fdividef(1.f, 1.f + __expf(-x));
}
__device__ __forceinline__ float tanh_fast(float x) {
    return 1.f - __fdividef(2.f, __expf(2.f * x) + 1.f);
}

// spin-wait on a per-chunk counter (one thread polls, CTA-wide release)
__device__ __forceinline__ void wait_flag(volatile int* flag, int target, int tid) {
    if (tid == 0) {
        while (*flag < target) { __nanosleep(200); }
    }
    __syncthreads();
    __threadfence();   // acquire: order subsequent gmem reads after the flag
}

// ---------------------------------------------------------------------------
// Owner-computes LSTM recurrence: 256 threads, batches (b0, b0+1).
// Thread (bat = tid>>7, unit u = tid&127) computes ALL FOUR gate dots for its
// unit itself -> no gate exchange, c stays in register, ONE barrier per step
// (h double-buffered by parity). Gate rows u, 128+u, 256+u, 384+u:
// cols 0..39 in regs (20 u64 per row, 160 fp32), cols 40..127 in smem
// (22 ulonglong2 per row, [q][row] layout, coalesced; h reads broadcast).
// ---------------------------------------------------------------------------
constexpr int REC4_SMEM = 22 * 512 * 16 + 2 * 2 * 128 * 4;   // 182,272 B

template<bool WRITE_ALL, bool PUBLISH, bool CONSUME>
__device__ __forceinline__ void rec_body4(const float* __restrict__ Whh,
                                          const float* __restrict__ xp,
                                          volatile int* cons_flags,
                                          float* smbase, int b0)
{
    ulonglong2* wsmq = (ulonglong2*)smbase;          // [22][512] ull2
    float*      hbase = smbase + 22 * 512 * 4;       // [2 parity][2 bat][128]

    const int tid = threadIdx.x;
    const int u   = tid & 127;
    const int bat = tid >> 7;
    const int b   = b0 + bat;
    const int r0 = u, r1 = 128 + u, r2 = 256 + u, r3 = 384 + u;

    // Register weights: cols 0..39 of all 4 gate rows (20 u64 each)
    u64 w0[20], w1[20], w2[20], w3[20];
    {
        const u64* p0 = (const u64*)(Whh + r0 * IN);
        const u64* p1 = (const u64*)(Whh + r1 * IN);
        const u64* p2 = (const u64*)(Whh + r2 * IN);
        const u64* p3 = (const u64*)(Whh + r3 * IN);
        #pragma unroll
        for (int i = 0; i < 20; i++) {
            w0[i] = p0[i]; w1[i] = p1[i]; w2[i] = p2[i]; w3[i] = p3[i];
        }
    }
    // Smem weights: cols 40..127 (22 ull2 per row); bat==0 threads fill all rows
    if (tid < 128) {
        const ulonglong2* q0 = (const ulonglong2*)(Whh + r0 * IN + 40);
        const ulonglong2* q1 = (const ulonglong2*)(Whh + r1 * IN + 40);
        const ulonglong2* q2 = (const ulonglong2*)(Whh + r2 * IN + 40);
        const ulonglong2* q3 = (const ulonglong2*)(Whh + r3 * IN + 40);
        #pragma unroll
        for (int q = 0; q < 22; q++) {
            wsmq[q * 512 + r0] = q0[q];
            wsmq[q * 512 + r1] = q1[q];
            wsmq[q * 512 + r2] = q2[q];
            wsmq[q * 512 + r3] = q3[q];
        }
    }
    hbase[tid] = 0.f;   // zero parity-0 buffers (256 floats)
    float c = 0.f;

    if (CONSUME) wait_flag(&cons_flags[0], NG, tid);   // chunk 0 ready

    float x0 = xp[((size_t)0 * B + b) * G + r0];
    float x1 = xp[((size_t)0 * B + b) * G + r1];
    float x2 = xp[((size_t)0 * B + b) * G + r2];
    float x3 = xp[((size_t)0 * B + b) * G + r3];
    __syncthreads();

    int p = 0;
    #pragma unroll 1
    for (int t = 0; t < T; t++) {
        const ulonglong2* hq = (const ulonglong2*)(hbase + p * 256 + bat * 128);
        u64 a0x = 0ull, a0y = 0ull, a1x = 0ull, a1y = 0ull;
        u64 a2x = 0ull, a2y = 0ull, a3x = 0ull, a3y = 0ull;
        #pragma unroll
        for (int q = 0; q < 10; q++) {
            const ulonglong2 hv = hq[q];
            a0x = ffma2(w0[2 * q], hv.x, a0x); a0y = ffma2(w0[2 * q + 1], hv.y, a0y);
            a1x = ffma2(w1[2 * q], hv.x, a1x); a1y = ffma2(w1[2 * q + 1], hv.y, a1y);
            a2x = ffma2(w2[2 * q], hv.x, a2x); a2y = ffma2(w2[2 * q + 1], hv.y, a2y);
            a3x = ffma2(w3[2 * q], hv.x, a3x); a3y = ffma2(w3[2 * q + 1], hv.y, a3y);
        }
        #pragma unroll
        for (int q = 0; q < 22; q++) {
            const ulonglong2 hv = hq[10 + q];
            const ulonglong2 v0 = wsmq[q * 512 + r0];
            a0x = ffma2(v0.x, hv.x, a0x); a0y = ffma2(v0.y, hv.y, a0y);
            const ulonglong2 v1 = wsmq[q * 512 + r1];
            a1x = ffma2(v1.x, hv.x, a1x); a1y = ffma2(v1.y, hv.y, a1y);
            const ulonglong2 v2 = wsmq[q * 512 + r2];
            a2x = ffma2(v2.x, hv.x, a2x); a2y = ffma2(v2.y, hv.y, a2y);
            const ulonglong2 v3 = wsmq[q * 512 + r3];
            a3x = ffma2(v3.x, hv.x, a3x); a3y = ffma2(v3.y, hv.y, a3y);
        }
        const float gi = hadd2(a0x) + hadd2(a0y) + x0;
        const float gf = hadd2(a1x) + hadd2(a1y) + x1;
        const float gg = hadd2(a2x) + hadd2(a2y) + x2;
        const float go = hadd2(a3x) + hadd2(a3y) + x3;
        const float iv = sigf(gi);
        const float fv = sigf(gf);
        const float gv = tanh_fast(gg);
        const float ov = sigf(go);
        c = fv * c + iv * gv;
        const float h = ov * tanh_fast(c);
        hbase[(1 ^ p) * 256 + bat * 128 + u] = h;
        if (WRITE_ALL) {
            g_hs[((size_t)t * B + b) * H + u] = h;
        } else if (t == T - 1) {
            g_hT[b * H + u] = h;
        }
        // prefetch next step's xproj (gated per-chunk if CONSUME)
        if (t + 1 < T) {
            if (CONSUME && (((t + 1) & (CH - 1)) == 0)) {
                wait_flag(&cons_flags[(t + 1) / CH], NG, tid);
            }
            const size_t base = ((size_t)(t + 1) * B + b) * G;
            x0 = xp[base + r0];
            x1 = xp[base + r1];
            x2 = xp[base + r2];
            x3 = xp[base + r3];
        }
        __syncthreads();
        if (PUBLISH && ((t & (CH - 1)) == CH - 1)) {
            __threadfence();          // release this chunk's g_hs
            __syncthreads();
            if (tid == 0) atomicAdd(&g_h0_done[t / CH], 1);
        }
        p ^= 1;
    }
}

// ---------------------------------------------------------------------------
// GEMM tile compute (64b x 64g, K=128) from smem.
// ---------------------------------------------------------------------------
__device__ __forceinline__ void gemm_tile(const float* Ws, const float* As,
                                          const float* bias, float* outp)
{
    const int tid  = threadIdx.x;
    const int bb   = tid >> 3;
    const int gblk = tid & 7;

    u64 acc[8];
    #pragma unroll
    for (int i = 0; i < 8; i++) acc[i] = 0ull;

    #pragma unroll 8
    for (int k = 0; k < 128; k++) {
        const u64 a0 = pack_dup(As[bb * 136 + k]);
        const u64 a1 = pack_dup(As[(bb + 32) * 136 + k]);
        const ulonglong2* wp = (const ulonglong2*)&Ws[k * 68 + gblk * 8];
        const ulonglong2 wlo = wp[0], whi = wp[1];
        acc[0] = ffma2(wlo.x, a0, acc[0]);
        acc[1] = ffma2(wlo.y, a0, acc[1]);
        acc[2] = ffma2(whi.x, a0, acc[2]);
        acc[3] = ffma2(whi.y, a0, acc[3]);
        acc[4] = ffma2(wlo.x, a1, acc[4]);
        acc[5] = ffma2(wlo.y, a1, acc[5]);
        acc[6] = ffma2(whi.x, a1, acc[6]);
        acc[7] = ffma2(whi.y, a1, acc[7]);
    }

    #pragma unroll
    for (int half = 0; half < 2; half++) {
        const int row = bb + half * 32;
        float4 o0, o1;
        float2 p0 = unpack2(acc[half * 4 + 0]);
        float2 p1 = unpack2(acc[half * 4 + 1]);
        float2 p2 = unpack2(acc[half * 4 + 2]);
        float2 p3 = unpack2(acc[half * 4 + 3]);
        o0.x = p0.x + bias[0]; o0.y = p0.y + bias[1];
        o0.z = p1.x + bias[2]; o0.w = p1.y + bias[3];
        o1.x = p2.x + bias[4]; o1.y = p2.y + bias[5];
        o1.z = p3.x + bias[6]; o1.w = p3.y + bias[7];
        float* op = outp + (size_t)row * G;
        ((float4*)op)[0] = o0;
        ((float4*)op)[1] = o1;
    }
}

constexpr int GEMM_SMEM  = (128 * 68 + 64 * 136) * 4;   // 69,632 B
constexpr int FUSED_SMEM = (GEMM_SMEM > REC4_SMEM) ? GEMM_SMEM : REC4_SMEM;

// ---------------------------------------------------------------------------
// Kernel: layer-0 input projection GEMM, TT=4 (best measured). Grid (T/4, 8).
// ---------------------------------------------------------------------------
constexpr int TT = 4;

__global__ __launch_bounds__(256)
void xproj_gemm0(const float* __restrict__ mapf, const float* __restrict__ pos,
                 const float* __restrict__ Wih,  const float* __restrict__ bih,
                 const float* __restrict__ bhh)
{
    extern __shared__ float sm[];
    float* Ws = sm;               // [128][68] k-major
    float* As = sm + 128 * 68;    // [64][136] row-major

    const int t0  = blockIdx.x * TT;
    const int gc  = blockIdx.y;
    const int tid = threadIdx.x;

    for (int idx = tid; idx < 64 * 128; idx += 256) {
        const int k = idx & 127;
        const int g = idx >> 7;
        Ws[k * 68 + g] = Wih[(gc * 64 + g) * IN + k];
    }

    const int gblk = tid & 7;
    const int gbase = gc * 64 + gblk * 8;
    float bias[8];
    #pragma unroll
    for (int i = 0; i < 8; i++) bias[i] = bih[gbase + i] + bhh[gbase + i];

    for (int tt = 0; tt < TT; tt++) {
        const int t = t0 + tt;
        __syncthreads();
        for (int idx = tid; idx < 64 * 128; idx += 256) {
            const int k = idx & 127;
            const int r = idx >> 7;
            const float v = (k < 126) ? mapf[((size_t)r * T + t) * 126 + k]
                                      : pos[((size_t)r * T + t) * 2 + (k - 126)];
            As[r * 136 + k] = v;
        }
        __syncthreads();
        gemm_tile(Ws, As, bias, g_xp0 + (size_t)t * B * G + gbase);
    }
}

// ---------------------------------------------------------------------------
// FUSED kernel (R11 topology): rec0 (32 CTAs, 2 batches, owner-computes) +
// gemm1 (80 CTAs) + rec1 (32 CTAs) = 144 CTAs at 1 CTA/SM <= 148 SMs ->
// wave-1 co-residency, acyclic flag chain rec0 -> h0 -> gemm -> xp1 -> rec1.
// ---------------------------------------------------------------------------
__global__ __launch_bounds__(256, 1)
void fused_pipeline(const float* __restrict__ Whh0,
                    const float* __restrict__ Wih1,
                    const float* __restrict__ bih1,
                    const float* __restrict__ bhh1,
                    const float* __restrict__ Whh1)
{
    extern __shared__ float sm[];
    const int tid = threadIdx.x;
    const int bid = blockIdx.x;

    if (bid < RECC0) {
        rec_body4<true, true, false>(Whh0, g_xp0, g_h0_done, sm, 2 * bid);
        return;
    }
    if (bid >= RECC0 + NG) {
        rec_body4<false, false, true>(Whh1, g_xp1, g_xp1_done, sm,
                                      2 * (bid - RECC0 - NG));
        return;
    }

    // ---- gemm role: xp1 from g_hs, chunk-gated ----
    const int idx = bid - RECC0;         // 0..NG-1
    const int gc  = idx & 7;
    const int sub = idx >> 3;            // 0..9
    float* Ws = sm;
    float* As = sm + 128 * 68;

    for (int i = tid; i < 64 * 128; i += 256) {
        const int k = i & 127;
        const int g = i >> 7;
        Ws[k * 68 + g] = Wih1[(gc * 64 + g) * IN + k];
    }

    const int gblk = tid & 7;
    const int gbase = gc * 64 + gblk * 8;
    float bias[8];
    #pragma unroll
    for (int i = 0; i < 8; i++) bias[i] = bih1[gbase + i] + bhh1[gbase + i];

    for (int c = 0; c < NCHUNK; c++) {
        wait_flag(&g_h0_done[c], RECC0, tid);

        for (int tl = sub; tl < CH; tl += 10) {
            const int t = c * CH + tl;
            __syncthreads();   // protect As from previous tile's readers
            const float4* src = (const float4*)(g_hs + (size_t)t * B * H);
            #pragma unroll
            for (int j = 0; j < 8; j++) {
                const int i4 = tid + j * 256;       // 0..2047
                const int r  = i4 >> 5;
                const int k4 = i4 & 31;
                ((float4*)&As[r * 136 + k4 * 4])[0] = src[i4];
            }
            __syncthreads();
            gemm_tile(Ws, As, bias, g_xp1 + (size_t)t * B * G + gbase);
        }
        __threadfence();          // release this chunk's g_xp1
        __syncthreads();
        if (tid == 0) atomicAdd(&g_xp1_done[c], 1);
    }
}

// ---------------------------------------------------------------------------
// MLP head: one CTA per batch row, 64 threads.
// ---------------------------------------------------------------------------
__global__ void head_kernel(const float* __restrict__ W1, const float* __restrict__ b1,
                            const float* __restrict__ lng, const float* __restrict__ lnb,
                            const float* __restrict__ W2, const float* __restrict__ b2,
                            float* __restrict__ out)
{
    __shared__ float hb[128];
    __shared__ float red[64];
    __shared__ float bc;
    const int b = blockIdx.x;
    const int j = threadIdx.x;

    hb[j]      = g_hT[b * H + j];
    hb[j + 64] = g_hT[b * H + 64 + j];
    __syncthreads();

    float acc = b1[j];
    #pragma unroll 8
    for (int k = 0; k < H; k++) acc += hb[k] * W1[j * H + k];

    red[j] = acc; __syncthreads();
    if (j == 0) { float s = 0.f; for (int k = 0; k < 64; k++) s += red[k]; bc = s * (1.f / 64.f); }
    __syncthreads();
    const float mu = bc;
    const float d  = acc - mu;

    red[j] = d * d; __syncthreads();
    if (j == 0) { float s = 0.f; for (int k = 0; k < 64; k++) s += red[k]; bc = s * (1.f / 64.f); }
    __syncthreads();
    const float var = bc;

    float v = d * rsqrtf(var + 1e-5f) * lng[j] + lnb[j];
    v = (v >= 0.f) ? v : 0.2f * v;

    red[j] = v * W2[j]; __syncthreads();
    if (j == 0) { float s = 0.f; for (int k = 0; k < 64; k++) s += red[k]; out[b] = s + b2[0]; }
}

// ---------------------------------------------------------------------------
// Launch: reset -> gemm0 -> fused(rec0 || gemm1 || rec1) -> head
// ---------------------------------------------------------------------------
extern "C" void kernel_launch(void* const* d_in, const int* in_sizes, int n_in,
                              void* d_out, int out_size)
{
    const float* mapf = (const float*)d_in[0];
    const float* pos  = (const float*)d_in[1];
    const float* Wih0 = (const float*)d_in[2];
    const float* Whh0 = (const float*)d_in[3];
    const float* bih0 = (const float*)d_in[4];
    const float* bhh0 = (const float*)d_in[5];
    const float* Wih1 = (const float*)d_in[6];
    const float* Whh1 = (const float*)d_in[7];
    const float* bih1 = (const float*)d_in[8];
    const float* bhh1 = (const float*)d_in[9];
    const float* W1   = (const float*)d_in[10];
    const float* b1   = (const float*)d_in[11];
    const float* lng  = (const float*)d_in[12];
    const float* lnb  = (const float*)d_in[13];
    const float* W2   = (const float*)d_in[14];
    const float* b2   = (const float*)d_in[15];
    float* out = (float*)d_out;

    cudaFuncSetAttribute((const void*)xproj_gemm0,
                         cudaFuncAttributeMaxDynamicSharedMemorySize, GEMM_SMEM);
    cudaFuncSetAttribute((const void*)fused_pipeline,
                         cudaFuncAttributeMaxDynamicSharedMemorySize, FUSED_SMEM);

    reset_flags<<<1, 1>>>();
    dim3 gg(T / TT, 8);
    xproj_gemm0<<<gg, 256, GEMM_SMEM>>>(mapf, pos, Wih0, bih0, bhh0);
    fused_pipeline<<<RECC0 + NG + RECC1, 256, FUSED_SMEM>>>(
        Whh0, Wih1, bih1, bhh1, Whh1);
    head_kernel<<<B, 64>>>(W1, b1, lng, lnb, W2, b2, out);
}

// round 15
// speedup vs baseline: 1.3489x; 1.3489x over previous
#include <cuda_runtime.h>
#include <math.h>

// Problem constants
constexpr int T  = 2048;
constexpr int B  = 64;
constexpr int H  = 128;
constexpr int G  = 512;   // 4*H gate rows
constexpr int IN = 128;

constexpr int CH     = 64;       // producer/consumer chunk (timesteps)
constexpr int NCHUNK = T / CH;   // 32
constexpr int RECC0  = 32;       // rec0 CTAs (2 batches each)
constexpr int NG     = 80;       // gemm CTAs (10 per gc)
constexpr int RECC1  = 32;       // rec1 CTAs (2 batches each)

typedef unsigned long long u64;

// ---------------------------------------------------------------------------
// Scratch (static __device__ arrays — no allocation in kernel_launch)
// ---------------------------------------------------------------------------
__device__ float g_xp0[(size_t)T * B * G];  // layer-0 input projections (+bias)
__device__ float g_xp1[(size_t)T * B * G];  // layer-1 input projections (+bias)
__device__ float g_hs[(size_t)T * B * H];   // layer-0 hidden states
__device__ float g_hT[B * H];               // final hidden of layer 1
// Per-chunk completion counters (drift-proof)
__device__ int   g_h0_done[NCHUNK];         // == RECC0 when chunk h0 published
__device__ int   g_xp1_done[NCHUNK];        // == NG when chunk xp1 published

__global__ void reset_flags() {
    for (int i = 0; i < NCHUNK; i++) { g_h0_done[i] = 0; g_xp1_done[i] = 0; }
}

// ---------------------------------------------------------------------------
// Packed fp32x2 helpers (PTX ISA 8.6+, sm_100+)
// ---------------------------------------------------------------------------
__device__ __forceinline__ u64 ffma2(u64 a, u64 b, u64 c) {
    u64 d;
    asm("fma.rn.f32x2 %0, %1, %2, %3;" : "=l"(d) : "l"(a), "l"(b), "l"(c));
    return d;
}
__device__ __forceinline__ u64 pack_dup(float a) {
    u64 d; asm("mov.b64 %0, {%1, %1};" : "=l"(d) : "f"(a)); return d;
}
__device__ __forceinline__ u64 pack2(float x, float y) {
    u64 d; asm("mov.b64 %0, {%1, %2};" : "=l"(d) : "f"(x), "f"(y)); return d;
}
__device__ __forceinline__ float2 unpack2(u64 a) {
    float2 r; asm("mov.b64 {%0, %1}, %2;" : "=f"(r.x), "=f"(r.y) : "l"(a)); return r;
}
__device__ __forceinline__ float hadd2(u64 a) {
    float2 r = unpack2(a); return r.x + r.y;
}
__device__ __forceinline__ float sigf(float x) {
    return __fdividef(1.f, 1.f + __expf(-x));
}
__device__ __forceinline__ float tanh_fast(float x) {
    return 1.f - __fdividef(2.f, __expf(2.f * x) + 1.f);
}

// spin-wait on a per-chunk counter (one thread polls, CTA-wide release)
__device__ __forceinline__ void wait_flag(volatile int* flag, int target, int tid) {
    if (tid == 0) {
        while (*flag < target) { __nanosleep(200); }
    }
    __syncthreads();
    __threadfence();   // acquire: order subsequent gmem reads after the flag
}

// ---------------------------------------------------------------------------
// 2-batch LSTM recurrence body (R11-proven layout). 256 threads, batches
// (b0, b0+1). Thread owns gate rows (tid, 256+tid) for BOTH batches.
// Weight cols 0..79 in regs (40 u64/row), cols 80..127 in smem (12 ull2/row).
// ---------------------------------------------------------------------------
constexpr int REC2_SMEM = 12 * 2 * 256 * 16 + 2 * 128 * 4 + 2 * 256 * 8; // 103,424 B

template<bool WRITE_ALL, bool PUBLISH, bool CONSUME>
__device__ __forceinline__ void rec_body2(const float* __restrict__ Whh,
                                          const float* __restrict__ xp,
                                          volatile int* cons_flags,
                                          float* smbase, int b0)
{
    ulonglong2* wsmq   = (ulonglong2*)smbase;            // [(q*2+row)*256 + tid]
    float*      hbuf0  = smbase + 12 * 2 * 256 * 4;      // 128 floats
    float*      hbuf1  = hbuf0 + 128;                    // 128 floats
    u64*        gat0   = (u64*)(hbuf1 + 128);            // 256 packed pairs
    u64*        gat1   = gat0 + 256;

    const int tid  = threadIdx.x;
    const int rowA = tid;
    const int rowB = 256 + tid;

    u64 wrA[40], wrB[40];
    {
        const u64* pa = (const u64*)(Whh + rowA * IN);
        const u64* pb = (const u64*)(Whh + rowB * IN);
        #pragma unroll
        for (int i = 0; i < 40; i++) { wrA[i] = pa[i]; wrB[i] = pb[i]; }
    }
    {
        const ulonglong2* ta = (const ulonglong2*)(Whh + rowA * IN + 80);
        const ulonglong2* tb = (const ulonglong2*)(Whh + rowB * IN + 80);
        #pragma unroll
        for (int q = 0; q < 12; q++) {
            wsmq[(q * 2 + 0) * 256 + tid] = ta[q];
            wsmq[(q * 2 + 1) * 256 + tid] = tb[q];
        }
    }
    if (tid < H) { hbuf0[tid] = 0.f; hbuf1[tid] = 0.f; }
    float cc = 0.f;   // cell state for (batch = tid>>7, unit = tid&127)

    if (CONSUME) wait_flag(&cons_flags[0], NG, tid);   // chunk 0 ready

    const float* xpb0 = xp + (size_t)b0 * G;
    const float* xpb1 = xp + (size_t)(b0 + 1) * G;
    float xa0 = xpb0[rowA], xb0 = xpb0[rowB];
    float xa1 = xpb1[rowA], xb1 = xpb1[rowB];
    const bool tanhB = (tid < 128);
    __syncthreads();

    #pragma unroll 1
    for (int t = 0; t < T; t++) {
        const ulonglong2* h0q = (const ulonglong2*)hbuf0;
        const ulonglong2* h1q = (const ulonglong2*)hbuf1;
        u64 aA0 = 0ull, aA1 = 0ull, aB0 = 0ull, aB1 = 0ull;   // batch0
        u64 cA0 = 0ull, cA1 = 0ull, cB0 = 0ull, cB1 = 0ull;   // batch1
        #pragma unroll
        for (int q = 0; q < 20; q++) {
            const ulonglong2 h0v = h0q[q];
            const ulonglong2 h1v = h1q[q];
            const u64 wa0 = wrA[2 * q], wa1 = wrA[2 * q + 1];
            const u64 wb0 = wrB[2 * q], wb1 = wrB[2 * q + 1];
            aA0 = ffma2(wa0, h0v.x, aA0);
            aA1 = ffma2(wa1, h0v.y, aA1);
            aB0 = ffma2(wb0, h0v.x, aB0);
            aB1 = ffma2(wb1, h0v.y, aB1);
            cA0 = ffma2(wa0, h1v.x, cA0);
            cA1 = ffma2(wa1, h1v.y, cA1);
            cB0 = ffma2(wb0, h1v.x, cB0);
            cB1 = ffma2(wb1, h1v.y, cB1);
        }
        #pragma unroll
        for (int q = 0; q < 12; q++) {
            const ulonglong2 h0v = h0q[20 + q];
            const ulonglong2 h1v = h1q[20 + q];
            const ulonglong2 wa = wsmq[(q * 2 + 0) * 256 + tid];
            const ulonglong2 wb = wsmq[(q * 2 + 1) * 256 + tid];
            aA0 = ffma2(wa.x, h0v.x, aA0);
            aA1 = ffma2(wa.y, h0v.y, aA1);
            aB0 = ffma2(wb.x, h0v.x, aB0);
            aB1 = ffma2(wb.y, h0v.y, aB1);
            cA0 = ffma2(wa.x, h1v.x, cA0);
            cA1 = ffma2(wa.y, h1v.y, cA1);
            cB0 = ffma2(wb.x, h1v.x, cB0);
            cB1 = ffma2(wb.y, h1v.y, cB1);
        }
        const float gA0 = hadd2(aA0) + hadd2(aA1) + xa0;
        const float gB0 = hadd2(aB0) + hadd2(aB1) + xb0;
        const float gA1 = hadd2(cA0) + hadd2(cA1) + xa1;
        const float gB1 = hadd2(cB0) + hadd2(cB1) + xb1;
        const float actA0 = sigf(gA0);
        const float actB0 = tanhB ? tanh_fast(gB0) : sigf(gB0);
        const float actA1 = sigf(gA1);
        const float actB1 = tanhB ? tanh_fast(gB1) : sigf(gB1);
        if (t + 1 < T) {
            if (CONSUME && (((t + 1) & (CH - 1)) == 0)) {
                wait_flag(&cons_flags[(t + 1) / CH], NG, tid);
            }
            const size_t off = (size_t)(t + 1) * (B * G);
            xa0 = xpb0[off + rowA]; xb0 = xpb0[off + rowB];
            xa1 = xpb1[off + rowA]; xb1 = xpb1[off + rowB];
        }
        gat0[tid] = pack2(actA0, actB0);
        gat1[tid] = pack2(actA1, actB1);
        __syncthreads();
        {
            const int unit = tid & 127;
            const int bat  = tid >> 7;
            u64*   gsel = bat ? gat1 : gat0;
            float* hsel = bat ? hbuf1 : hbuf0;
            const float2 ig = unpack2(gsel[unit]);          // (i, g)
            const float2 fo = unpack2(gsel[unit + 128]);    // (f, o)
            cc = fo.x * cc + ig.x * ig.y;
            const float h = fo.y * tanh_fast(cc);
            hsel[unit] = h;
            if (WRITE_ALL) {
                g_hs[((size_t)t * B + b0 + bat) * H + unit] = h;
            } else if (t == T - 1) {
                g_hT[(b0 + bat) * H + unit] = h;
            }
        }
        __syncthreads();
        if (PUBLISH && ((t & (CH - 1)) == CH - 1)) {
            __threadfence();          // release this chunk's g_hs
            __syncthreads();
            if (tid == 0) atomicAdd(&g_h0_done[t / CH], 1);
        }
    }
}

// ---------------------------------------------------------------------------
// GEMM tile compute (64b x 64g, K=128) from smem.
// ---------------------------------------------------------------------------
__device__ __forceinline__ void gemm_tile(const float* Ws, const float* As,
                                          const float* bias, float* outp)
{
    const int tid  = threadIdx.x;
    const int bb   = tid >> 3;
    const int gblk = tid & 7;

    u64 acc[8];
    #pragma unroll
    for (int i = 0; i < 8; i++) acc[i] = 0ull;

    #pragma unroll 8
    for (int k = 0; k < 128; k++) {
        const u64 a0 = pack_dup(As[bb * 136 + k]);
        const u64 a1 = pack_dup(As[(bb + 32) * 136 + k]);
        const ulonglong2* wp = (const ulonglong2*)&Ws[k * 68 + gblk * 8];
        const ulonglong2 wlo = wp[0], whi = wp[1];
        acc[0] = ffma2(wlo.x, a0, acc[0]);
        acc[1] = ffma2(wlo.y, a0, acc[1]);
        acc[2] = ffma2(whi.x, a0, acc[2]);
        acc[3] = ffma2(whi.y, a0, acc[3]);
        acc[4] = ffma2(wlo.x, a1, acc[4]);
        acc[5] = ffma2(wlo.y, a1, acc[5]);
        acc[6] = ffma2(whi.x, a1, acc[6]);
        acc[7] = ffma2(whi.y, a1, acc[7]);
    }

    #pragma unroll
    for (int half = 0; half < 2; half++) {
        const int row = bb + half * 32;
        float4 o0, o1;
        float2 p0 = unpack2(acc[half * 4 + 0]);
        float2 p1 = unpack2(acc[half * 4 + 1]);
        float2 p2 = unpack2(acc[half * 4 + 2]);
        float2 p3 = unpack2(acc[half * 4 + 3]);
        o0.x = p0.x + bias[0]; o0.y = p0.y + bias[1];
        o0.z = p1.x + bias[2]; o0.w = p1.y + bias[3];
        o1.x = p2.x + bias[4]; o1.y = p2.y + bias[5];
        o1.z = p3.x + bias[6]; o1.w = p3.y + bias[7];
        float* op = outp + (size_t)row * G;
        ((float4*)op)[0] = o0;
        ((float4*)op)[1] = o1;
    }
}

constexpr int GEMM_SMEM  = (128 * 68 + 64 * 136) * 4;        // 69,632 B
constexpr int GEMMF_SMEM = (128 * 68 + 2 * 64 * 136) * 4;    // 104,448 B (dbl-buf As)
constexpr int FUSED_SMEM = (GEMMF_SMEM > REC2_SMEM) ? GEMMF_SMEM : REC2_SMEM;

// ---------------------------------------------------------------------------
// Kernel: layer-0 input projection GEMM, TT=4 (proven config). Grid (T/4, 8).
// ---------------------------------------------------------------------------
constexpr int TT = 4;

__global__ __launch_bounds__(256)
void xproj_gemm0(const float* __restrict__ mapf, const float* __restrict__ pos,
                 const float* __restrict__ Wih,  const float* __restrict__ bih,
                 const float* __restrict__ bhh)
{
    extern __shared__ float sm[];
    float* Ws = sm;               // [128][68] k-major
    float* As = sm + 128 * 68;    // [64][136] row-major

    const int t0  = blockIdx.x * TT;
    const int gc  = blockIdx.y;
    const int tid = threadIdx.x;

    for (int idx = tid; idx < 64 * 128; idx += 256) {
        const int k = idx & 127;
        const int g = idx >> 7;
        Ws[k * 68 + g] = Wih[(gc * 64 + g) * IN + k];
    }

    const int gblk = tid & 7;
    const int gbase = gc * 64 + gblk * 8;
    float bias[8];
    #pragma unroll
    for (int i = 0; i < 8; i++) bias[i] = bih[gbase + i] + bhh[gbase + i];

    for (int tt = 0; tt < TT; tt++) {
        const int t = t0 + tt;
        __syncthreads();
        for (int idx = tid; idx < 64 * 128; idx += 256) {
            const int k = idx & 127;
            const int r = idx >> 7;
            const float v = (k < 126) ? mapf[((size_t)r * T + t) * 126 + k]
                                      : pos[((size_t)r * T + t) * 2 + (k - 126)];
            As[r * 136 + k] = v;
        }
        __syncthreads();
        gemm_tile(Ws, As, bias, g_xp0 + (size_t)t * B * G + gbase);
    }
}

// ---------------------------------------------------------------------------
// FUSED kernel (R11 topology, CH=64): rec0 (32 CTAs, 2 batches) + gemm1
// (80 CTAs, double-buffered As pipeline) + rec1 (32 CTAs) = 144 CTAs at
// 1 CTA/SM <= 148 SMs -> wave-1 co-residency; acyclic flag chain
// rec0 -> h0_done -> gemm -> xp1_done -> rec1.
// ---------------------------------------------------------------------------
__global__ __launch_bounds__(256, 1)
void fused_pipeline(const float* __restrict__ Whh0,
                    const float* __restrict__ Wih1,
                    const float* __restrict__ bih1,
                    const float* __restrict__ bhh1,
                    const float* __restrict__ Whh1)
{
    extern __shared__ float sm[];
    const int tid = threadIdx.x;
    const int bid = blockIdx.x;

    if (bid < RECC0) {
        rec_body2<true, true, false>(Whh0, g_xp0, g_h0_done, sm, 2 * bid);
        return;
    }
    if (bid >= RECC0 + NG) {
        rec_body2<false, false, true>(Whh1, g_xp1, g_xp1_done, sm,
                                      2 * (bid - RECC0 - NG));
        return;
    }

    // ---- gemm role: xp1 from g_hs, chunk-gated, software-pipelined ----
    const int idx = bid - RECC0;         // 0..NG-1
    const int gc  = idx & 7;
    const int sub = idx >> 3;            // 0..9
    float* Ws  = sm;                     // [128][68]
    float* AsA = sm + 128 * 68;          // [64][136]
    float* AsB = AsA + 64 * 136;         // [64][136]

    for (int i = tid; i < 64 * 128; i += 256) {
        const int k = i & 127;
        const int g = i >> 7;
        Ws[k * 68 + g] = Wih1[(gc * 64 + g) * IN + k];
    }

    const int gblk = tid & 7;
    const int gbase = gc * 64 + gblk * 8;
    float bias[8];
    #pragma unroll
    for (int i = 0; i < 8; i++) bias[i] = bih1[gbase + i] + bhh1[gbase + i];

    // addressing for As fill: thread covers 8 float4 slots
    const int fr  = tid >> 5;            // base row group (i4>>5 for j=0)
    const int fk4 = tid & 31;

    for (int c = 0; c < NCHUNK; c++) {
        wait_flag(&g_h0_done[c], RECC0, tid);

        // tiles this CTA handles in chunk c: t = c*CH + sub + i*10
        // Prime: load first tile into AsA.
        int tl0 = sub;
        {
            const int t = c * CH + tl0;
            const float4* src = (const float4*)(g_hs + (size_t)t * B * H);
            #pragma unroll
            for (int j = 0; j < 8; j++) {
                const int i4 = tid + j * 256;
                ((float4*)&AsA[(i4 >> 5) * 136 + (i4 & 31) * 4])[0] = src[i4];
            }
        }
        __syncthreads();

        float* cur = AsA;
        float* nxt = AsB;
        for (int tl = tl0; tl < CH; tl += 10) {
            const int t = c * CH + tl;
            const int tn = tl + 10;
            // prefetch next tile into registers (hidden behind compute)
            float4 pf[8];
            if (tn < CH) {
                const float4* srcn =
                    (const float4*)(g_hs + (size_t)(c * CH + tn) * B * H);
                #pragma unroll
                for (int j = 0; j < 8; j++) pf[j] = srcn[tid + j * 256];
            }
            gemm_tile(Ws, cur, bias, g_xp1 + (size_t)t * B * G + gbase);
            if (tn < CH) {
                #pragma unroll
                for (int j = 0; j < 8; j++) {
                    const int i4 = tid + j * 256;
                    ((float4*)&nxt[(i4 >> 5) * 136 + (i4 & 31) * 4])[0] = pf[j];
                }
            }
            __syncthreads();
            float* tmp = cur; cur = nxt; nxt = tmp;
        }
        __threadfence();          // release this chunk's g_xp1
        __syncthreads();
        if (tid == 0) atomicAdd(&g_xp1_done[c], 1);
    }
    (void)fr; (void)fk4;
}

// ---------------------------------------------------------------------------
// MLP head: one CTA per batch row, 64 threads.
// ---------------------------------------------------------------------------
__global__ void head_kernel(const float* __restrict__ W1, const float* __restrict__ b1,
                            const float* __restrict__ lng, const float* __restrict__ lnb,
                            const float* __restrict__ W2, const float* __restrict__ b2,
                            float* __restrict__ out)
{
    __shared__ float hb[128];
    __shared__ float red[64];
    __shared__ float bc;
    const int b = blockIdx.x;
    const int j = threadIdx.x;

    hb[j]      = g_hT[b * H + j];
    hb[j + 64] = g_hT[b * H + 64 + j];
    __syncthreads();

    float acc = b1[j];
    #pragma unroll 8
    for (int k = 0; k < H; k++) acc += hb[k] * W1[j * H + k];

    red[j] = acc; __syncthreads();
    if (j == 0) { float s = 0.f; for (int k = 0; k < 64; k++) s += red[k]; bc = s * (1.f / 64.f); }
    __syncthreads();
    const float mu = bc;
    const float d  = acc - mu;

    red[j] = d * d; __syncthreads();
    if (j == 0) { float s = 0.f; for (int k = 0; k < 64; k++) s += red[k]; bc = s * (1.f / 64.f); }
    __syncthreads();
    const float var = bc;

    float v = d * rsqrtf(var + 1e-5f) * lng[j] + lnb[j];
    v = (v >= 0.f) ? v : 0.2f * v;

    red[j] = v * W2[j]; __syncthreads();
    if (j == 0) { float s = 0.f; for (int k = 0; k < 64; k++) s += red[k]; out[b] = s + b2[0]; }
}

// ---------------------------------------------------------------------------
// Launch: reset -> gemm0 -> fused(rec0 || gemm1 || rec1) -> head
// ---------------------------------------------------------------------------
extern "C" void kernel_launch(void* const* d_in, const int* in_sizes, int n_in,
                              void* d_out, int out_size)
{
    const float* mapf = (const float*)d_in[0];
    const float* pos  = (const float*)d_in[1];
    const float* Wih0 = (const float*)d_in[2];
    const float* Whh0 = (const float*)d_in[3];
    const float* bih0 = (const float*)d_in[4];
    const float* bhh0 = (const float*)d_in[5];
    const float* Wih1 = (const float*)d_in[6];
    const float* Whh1 = (const float*)d_in[7];
    const float* bih1 = (const float*)d_in[8];
    const float* bhh1 = (const float*)d_in[9];
    const float* W1   = (const float*)d_in[10];
    const float* b1   = (const float*)d_in[11];
    const float* lng  = (const float*)d_in[12];
    const float* lnb  = (const float*)d_in[13];
    const float* W2   = (const float*)d_in[14];
    const float* b2   = (const float*)d_in[15];
    float* out = (float*)d_out;

    cudaFuncSetAttribute((const void*)xproj_gemm0,
                         cudaFuncAttributeMaxDynamicSharedMemorySize, GEMM_SMEM);
    cudaFuncSetAttribute((const void*)fused_pipeline,
                         cudaFuncAttributeMaxDynamicSharedMemorySize, FUSED_SMEM);

    reset_flags<<<1, 1>>>();
    dim3 gg(T / TT, 8);
    xproj_gemm0<<<gg, 256, GEMM_SMEM>>>(mapf, pos, Wih0, bih0, bhh0);
    fused_pipeline<<<RECC0 + NG + RECC1, 256, FUSED_SMEM>>>(
        Whh0, Wih1, bih1, bhh1, Whh1);
    head_kernel<<<B, 64>>>(W1, b1, lng, lnb, W2, b2, out);
}

// round 16
// speedup vs baseline: 1.4361x; 1.0647x over previous
#include <cuda_runtime.h>
#include <math.h>

// Problem constants
constexpr int T  = 2048;
constexpr int B  = 64;
constexpr int H  = 128;
constexpr int G  = 512;   // 4*H gate rows
constexpr int IN = 128;

constexpr int CH     = 64;       // producer/consumer chunk (timesteps)
constexpr int NCHUNK = T / CH;   // 32
constexpr int RECC0  = 32;       // rec0 CTAs (2 batches each)
constexpr int NG     = 80;       // gemm CTAs (10 per gc)
constexpr int RECC1  = 32;       // rec1 CTAs (2 batches each)

typedef unsigned long long u64;

// ---------------------------------------------------------------------------
// Scratch (static __device__ arrays — no allocation in kernel_launch)
// ---------------------------------------------------------------------------
__device__ float g_xp0[(size_t)T * B * G];  // layer-0 input projections (+bias)
__device__ float g_xp1[(size_t)T * B * G];  // layer-1 input projections (+bias)
__device__ float g_hs[(size_t)T * B * H];   // layer-0 hidden states
__device__ float g_hT[B * H];               // final hidden of layer 1
// Per-chunk completion counters (drift-proof)
__device__ int   g_h0_done[NCHUNK];         // == RECC0 when chunk h0 published
__device__ int   g_xp1_done[NCHUNK];        // == NG when chunk xp1 published

__global__ void reset_flags() {
    for (int i = 0; i < NCHUNK; i++) { g_h0_done[i] = 0; g_xp1_done[i] = 0; }
}

// ---------------------------------------------------------------------------
// Packed fp32x2 helpers (PTX ISA 8.6+, sm_100+)
// ---------------------------------------------------------------------------
__device__ __forceinline__ u64 ffma2(u64 a, u64 b, u64 c) {
    u64 d;
    asm("fma.rn.f32x2 %0, %1, %2, %3;" : "=l"(d) : "l"(a), "l"(b), "l"(c));
    return d;
}
__device__ __forceinline__ u64 pack_dup(float a) {
    u64 d; asm("mov.b64 %0, {%1, %1};" : "=l"(d) : "f"(a)); return d;
}
__device__ __forceinline__ u64 pack2(float x, float y) {
    u64 d; asm("mov.b64 %0, {%1, %2};" : "=l"(d) : "f"(x), "f"(y)); return d;
}
__device__ __forceinline__ float2 unpack2(u64 a) {
    float2 r; asm("mov.b64 {%0, %1}, %2;" : "=f"(r.x), "=f"(r.y) : "l"(a)); return r;
}
__device__ __forceinline__ float hadd2(u64 a) {
    float2 r = unpack2(a); return r.x + r.y;
}
__device__ __forceinline__ float sigf(float x) {
    return __fdividef(1.f, 1.f + __expf(-x));
}
__device__ __forceinline__ float tanh_fast(float x) {
    return 1.f - __fdividef(2.f, __expf(2.f * x) + 1.f);
}

// spin-wait on a per-chunk counter (one thread polls, CTA-wide release)
__device__ __forceinline__ void wait_flag(volatile int* flag, int target, int tid) {
    if (tid == 0) {
        while (*flag < target) { __nanosleep(200); }
    }
    __syncthreads();
    __threadfence();   // acquire: order subsequent gmem reads after the flag
}

// ---------------------------------------------------------------------------
// 2-batch LSTM recurrence body (R11/R15-proven layout, unchanged). 256 thr,
// batches (b0, b0+1). Thread owns gate rows (tid, 256+tid) for BOTH batches.
// Weight cols 0..79 in regs (40 u64/row), cols 80..127 in smem (12 ull2/row).
// ---------------------------------------------------------------------------
constexpr int REC2_SMEM = 12 * 2 * 256 * 16 + 2 * 128 * 4 + 2 * 256 * 8; // 103,424 B

template<bool WRITE_ALL, bool PUBLISH, bool CONSUME>
__device__ __forceinline__ void rec_body2(const float* __restrict__ Whh,
                                          const float* __restrict__ xp,
                                          volatile int* cons_flags,
                                          float* smbase, int b0)
{
    ulonglong2* wsmq   = (ulonglong2*)smbase;            // [(q*2+row)*256 + tid]
    float*      hbuf0  = smbase + 12 * 2 * 256 * 4;      // 128 floats
    float*      hbuf1  = hbuf0 + 128;                    // 128 floats
    u64*        gat0   = (u64*)(hbuf1 + 128);            // 256 packed pairs
    u64*        gat1   = gat0 + 256;

    const int tid  = threadIdx.x;
    const int rowA = tid;
    const int rowB = 256 + tid;

    u64 wrA[40], wrB[40];
    {
        const u64* pa = (const u64*)(Whh + rowA * IN);
        const u64* pb = (const u64*)(Whh + rowB * IN);
        #pragma unroll
        for (int i = 0; i < 40; i++) { wrA[i] = pa[i]; wrB[i] = pb[i]; }
    }
    {
        const ulonglong2* ta = (const ulonglong2*)(Whh + rowA * IN + 80);
        const ulonglong2* tb = (const ulonglong2*)(Whh + rowB * IN + 80);
        #pragma unroll
        for (int q = 0; q < 12; q++) {
            wsmq[(q * 2 + 0) * 256 + tid] = ta[q];
            wsmq[(q * 2 + 1) * 256 + tid] = tb[q];
        }
    }
    if (tid < H) { hbuf0[tid] = 0.f; hbuf1[tid] = 0.f; }
    float cc = 0.f;   // cell state for (batch = tid>>7, unit = tid&127)

    if (CONSUME) wait_flag(&cons_flags[0], NG, tid);   // chunk 0 ready

    const float* xpb0 = xp + (size_t)b0 * G;
    const float* xpb1 = xp + (size_t)(b0 + 1) * G;
    float xa0 = xpb0[rowA], xb0 = xpb0[rowB];
    float xa1 = xpb1[rowA], xb1 = xpb1[rowB];
    const bool tanhB = (tid < 128);
    __syncthreads();

    #pragma unroll 1
    for (int t = 0; t < T; t++) {
        const ulonglong2* h0q = (const ulonglong2*)hbuf0;
        const ulonglong2* h1q = (const ulonglong2*)hbuf1;
        u64 aA0 = 0ull, aA1 = 0ull, aB0 = 0ull, aB1 = 0ull;   // batch0
        u64 cA0 = 0ull, cA1 = 0ull, cB0 = 0ull, cB1 = 0ull;   // batch1
        #pragma unroll
        for (int q = 0; q < 20; q++) {
            const ulonglong2 h0v = h0q[q];
            const ulonglong2 h1v = h1q[q];
            const u64 wa0 = wrA[2 * q], wa1 = wrA[2 * q + 1];
            const u64 wb0 = wrB[2 * q], wb1 = wrB[2 * q + 1];
            aA0 = ffma2(wa0, h0v.x, aA0);
            aA1 = ffma2(wa1, h0v.y, aA1);
            aB0 = ffma2(wb0, h0v.x, aB0);
            aB1 = ffma2(wb1, h0v.y, aB1);
            cA0 = ffma2(wa0, h1v.x, cA0);
            cA1 = ffma2(wa1, h1v.y, cA1);
            cB0 = ffma2(wb0, h1v.x, cB0);
            cB1 = ffma2(wb1, h1v.y, cB1);
        }
        #pragma unroll
        for (int q = 0; q < 12; q++) {
            const ulonglong2 h0v = h0q[20 + q];
            const ulonglong2 h1v = h1q[20 + q];
            const ulonglong2 wa = wsmq[(q * 2 + 0) * 256 + tid];
            const ulonglong2 wb = wsmq[(q * 2 + 1) * 256 + tid];
            aA0 = ffma2(wa.x, h0v.x, aA0);
            aA1 = ffma2(wa.y, h0v.y, aA1);
            aB0 = ffma2(wb.x, h0v.x, aB0);
            aB1 = ffma2(wb.y, h0v.y, aB1);
            cA0 = ffma2(wa.x, h1v.x, cA0);
            cA1 = ffma2(wa.y, h1v.y, cA1);
            cB0 = ffma2(wb.x, h1v.x, cB0);
            cB1 = ffma2(wb.y, h1v.y, cB1);
        }
        const float gA0 = hadd2(aA0) + hadd2(aA1) + xa0;
        const float gB0 = hadd2(aB0) + hadd2(aB1) + xb0;
        const float gA1 = hadd2(cA0) + hadd2(cA1) + xa1;
        const float gB1 = hadd2(cB0) + hadd2(cB1) + xb1;
        const float actA0 = sigf(gA0);
        const float actB0 = tanhB ? tanh_fast(gB0) : sigf(gB0);
        const float actA1 = sigf(gA1);
        const float actB1 = tanhB ? tanh_fast(gB1) : sigf(gB1);
        if (t + 1 < T) {
            if (CONSUME && (((t + 1) & (CH - 1)) == 0)) {
                wait_flag(&cons_flags[(t + 1) / CH], NG, tid);
            }
            const size_t off = (size_t)(t + 1) * (B * G);
            xa0 = xpb0[off + rowA]; xb0 = xpb0[off + rowB];
            xa1 = xpb1[off + rowA]; xb1 = xpb1[off + rowB];
        }
        gat0[tid] = pack2(actA0, actB0);
        gat1[tid] = pack2(actA1, actB1);
        __syncthreads();
        {
            const int unit = tid & 127;
            const int bat  = tid >> 7;
            u64*   gsel = bat ? gat1 : gat0;
            float* hsel = bat ? hbuf1 : hbuf0;
            const float2 ig = unpack2(gsel[unit]);          // (i, g)
            const float2 fo = unpack2(gsel[unit + 128]);    // (f, o)
            cc = fo.x * cc + ig.x * ig.y;
            const float h = fo.y * tanh_fast(cc);
            hsel[unit] = h;
            if (WRITE_ALL) {
                g_hs[((size_t)t * B + b0 + bat) * H + unit] = h;
            } else if (t == T - 1) {
                g_hT[(b0 + bat) * H + unit] = h;
            }
        }
        __syncthreads();
        if (PUBLISH && ((t & (CH - 1)) == CH - 1)) {
            __threadfence();          // release this chunk's g_hs
            __syncthreads();
            if (tid == 0) atomicAdd(&g_h0_done[t / CH], 1);
        }
    }
}

// ---------------------------------------------------------------------------
// 4-TIMESTEP GEMM GROUP: computes tiles for 4 consecutive timesteps with ONE
// weight read per k (amortizes the binding smem weight-port traffic 4x).
// Ws: [128][68] k-major. As4: [4][64][136]. Per thread: 32 outputs
// (4 tt x 2 rows x 8 gate cols), 32 u64 accumulators, 32 FFMA2 per k.
// ---------------------------------------------------------------------------
constexpr int AS_T  = 64 * 136;              // floats per timestep slab
constexpr int GEMM4_SMEM = (128 * 68 + 4 * AS_T) * 4;   // 174,080 B

__device__ __forceinline__ void gemm_group4(const float* Ws, const float* As4,
                                            const float* bias, float* outbase)
{
    const int tid  = threadIdx.x;
    const int bb   = tid >> 3;
    const int gblk = tid & 7;

    u64 acc[4][8];
    #pragma unroll
    for (int tt = 0; tt < 4; tt++)
        #pragma unroll
        for (int i = 0; i < 8; i++) acc[tt][i] = 0ull;

    #pragma unroll 4
    for (int k = 0; k < 128; k++) {
        const ulonglong2* wp = (const ulonglong2*)&Ws[k * 68 + gblk * 8];
        const ulonglong2 wlo = wp[0], whi = wp[1];
        #pragma unroll
        for (int tt = 0; tt < 4; tt++) {
            const float* As = As4 + tt * AS_T;
            const u64 a0 = pack_dup(As[bb * 136 + k]);
            const u64 a1 = pack_dup(As[(bb + 32) * 136 + k]);
            acc[tt][0] = ffma2(wlo.x, a0, acc[tt][0]);
            acc[tt][1] = ffma2(wlo.y, a0, acc[tt][1]);
            acc[tt][2] = ffma2(whi.x, a0, acc[tt][2]);
            acc[tt][3] = ffma2(whi.y, a0, acc[tt][3]);
            acc[tt][4] = ffma2(wlo.x, a1, acc[tt][4]);
            acc[tt][5] = ffma2(wlo.y, a1, acc[tt][5]);
            acc[tt][6] = ffma2(whi.x, a1, acc[tt][6]);
            acc[tt][7] = ffma2(whi.y, a1, acc[tt][7]);
        }
    }

    #pragma unroll
    for (int tt = 0; tt < 4; tt++) {
        #pragma unroll
        for (int half = 0; half < 2; half++) {
            const int row = bb + half * 32;
            float4 o0, o1;
            float2 p0 = unpack2(acc[tt][half * 4 + 0]);
            float2 p1 = unpack2(acc[tt][half * 4 + 1]);
            float2 p2 = unpack2(acc[tt][half * 4 + 2]);
            float2 p3 = unpack2(acc[tt][half * 4 + 3]);
            o0.x = p0.x + bias[0]; o0.y = p0.y + bias[1];
            o0.z = p1.x + bias[2]; o0.w = p1.y + bias[3];
            o1.x = p2.x + bias[4]; o1.y = p2.y + bias[5];
            o1.z = p3.x + bias[6]; o1.w = p3.y + bias[7];
            float* op = outbase + (size_t)tt * B * G + (size_t)row * G;
            ((float4*)op)[0] = o0;
            ((float4*)op)[1] = o1;
        }
    }
}

// ---------------------------------------------------------------------------
// Kernel: layer-0 input projection GEMM, 4 timesteps/CTA with weight-amortized
// group compute. Grid (T/4, 8), 256 threads, 1 CTA/SM.
// ---------------------------------------------------------------------------
__global__ __launch_bounds__(256)
void xproj_gemm0(const float* __restrict__ mapf, const float* __restrict__ pos,
                 const float* __restrict__ Wih,  const float* __restrict__ bih,
                 const float* __restrict__ bhh)
{
    extern __shared__ float sm[];
    float* Ws  = sm;               // [128][68] k-major
    float* As4 = sm + 128 * 68;    // [4][64][136]

    const int t0  = blockIdx.x * 4;
    const int gc  = blockIdx.y;
    const int tid = threadIdx.x;

    for (int idx = tid; idx < 64 * 128; idx += 256) {
        const int k = idx & 127;
        const int g = idx >> 7;
        Ws[k * 68 + g] = Wih[(gc * 64 + g) * IN + k];
    }
    // Fill As4 for 4 timesteps
    for (int idx = tid; idx < 4 * 64 * 128; idx += 256) {
        const int tt = idx >> 13;
        const int rem = idx & 8191;
        const int k = rem & 127;
        const int r = rem >> 7;
        const int t = t0 + tt;
        const float v = (k < 126) ? mapf[((size_t)r * T + t) * 126 + k]
                                  : pos[((size_t)r * T + t) * 2 + (k - 126)];
        As4[tt * AS_T + r * 136 + k] = v;
    }

    const int gblk = tid & 7;
    const int gbase = gc * 64 + gblk * 8;
    float bias[8];
    #pragma unroll
    for (int i = 0; i < 8; i++) bias[i] = bih[gbase + i] + bhh[gbase + i];
    __syncthreads();

    gemm_group4(Ws, As4, bias, g_xp0 + (size_t)t0 * B * G + gbase);
}

constexpr int FUSED_SMEM = (GEMM4_SMEM > REC2_SMEM) ? GEMM4_SMEM : REC2_SMEM;

// ---------------------------------------------------------------------------
// FUSED kernel (R15 topology, CH=64): rec0 (32 CTAs, 2 batches) + gemm1
// (80 CTAs, weight-amortized 4-timestep groups) + rec1 (32 CTAs) = 144 CTAs
// at 1 CTA/SM <= 148 SMs -> wave-1 co-residency; acyclic flag chain
// rec0 -> h0_done -> gemm -> xp1_done -> rec1.
// ---------------------------------------------------------------------------
__global__ __launch_bounds__(256, 1)
void fused_pipeline(const float* __restrict__ Whh0,
                    const float* __restrict__ Wih1,
                    const float* __restrict__ bih1,
                    const float* __restrict__ bhh1,
                    const float* __restrict__ Whh1)
{
    extern __shared__ float sm[];
    const int tid = threadIdx.x;
    const int bid = blockIdx.x;

    if (bid < RECC0) {
        rec_body2<true, true, false>(Whh0, g_xp0, g_h0_done, sm, 2 * bid);
        return;
    }
    if (bid >= RECC0 + NG) {
        rec_body2<false, false, true>(Whh1, g_xp1, g_xp1_done, sm,
                                      2 * (bid - RECC0 - NG));
        return;
    }

    // ---- gemm role: xp1 from g_hs, chunk-gated, 4-timestep groups ----
    const int idx = bid - RECC0;         // 0..NG-1
    const int gc  = idx & 7;
    const int sub = idx >> 3;            // 0..9
    float* Ws  = sm;                     // [128][68]
    float* As4 = sm + 128 * 68;          // [4][64][136]

    for (int i = tid; i < 64 * 128; i += 256) {
        const int k = i & 127;
        const int g = i >> 7;
        Ws[k * 68 + g] = Wih1[(gc * 64 + g) * IN + k];
    }

    const int gblk = tid & 7;
    const int gbase = gc * 64 + gblk * 8;
    float bias[8];
    #pragma unroll
    for (int i = 0; i < 8; i++) bias[i] = bih1[gbase + i] + bhh1[gbase + i];

    constexpr int NGROUP = CH / 4;       // 16 groups per chunk
    for (int c = 0; c < NCHUNK; c++) {
        wait_flag(&g_h0_done[c], RECC0, tid);

        for (int g = sub; g < NGROUP; g += 10) {
            const int tbase = c * CH + g * 4;
            __syncthreads();   // protect As4 from previous group's readers
            #pragma unroll
            for (int tt = 0; tt < 4; tt++) {
                const float4* src =
                    (const float4*)(g_hs + (size_t)(tbase + tt) * B * H);
                #pragma unroll
                for (int j = 0; j < 8; j++) {
                    const int i4 = tid + j * 256;
                    ((float4*)&As4[tt * AS_T + (i4 >> 5) * 136 + (i4 & 31) * 4])[0]
                        = src[i4];
                }
            }
            __syncthreads();
            gemm_group4(Ws, As4, bias, g_xp1 + (size_t)tbase * B * G + gbase);
        }
        __threadfence();          // release this chunk's g_xp1
        __syncthreads();
        if (tid == 0) atomicAdd(&g_xp1_done[c], 1);
    }
}

// ---------------------------------------------------------------------------
// MLP head: one CTA per batch row, 64 threads.
// ---------------------------------------------------------------------------
__global__ void head_kernel(const float* __restrict__ W1, const float* __restrict__ b1,
                            const float* __restrict__ lng, const float* __restrict__ lnb,
                            const float* __restrict__ W2, const float* __restrict__ b2,
                            float* __restrict__ out)
{
    __shared__ float hb[128];
    __shared__ float red[64];
    __shared__ float bc;
    const int b = blockIdx.x;
    const int j = threadIdx.x;

    hb[j]      = g_hT[b * H + j];
    hb[j + 64] = g_hT[b * H + 64 + j];
    __syncthreads();

    float acc = b1[j];
    #pragma unroll 8
    for (int k = 0; k < H; k++) acc += hb[k] * W1[j * H + k];

    red[j] = acc; __syncthreads();
    if (j == 0) { float s = 0.f; for (int k = 0; k < 64; k++) s += red[k]; bc = s * (1.f / 64.f); }
    __syncthreads();
    const float mu = bc;
    const float d  = acc - mu;

    red[j] = d * d; __syncthreads();
    if (j == 0) { float s = 0.f; for (int k = 0; k < 64; k++) s += red[k]; bc = s * (1.f / 64.f); }
    __syncthreads();
    const float var = bc;

    float v = d * rsqrtf(var + 1e-5f) * lng[j] + lnb[j];
    v = (v >= 0.f) ? v : 0.2f * v;

    red[j] = v * W2[j]; __syncthreads();
    if (j == 0) { float s = 0.f; for (int k = 0; k < 64; k++) s += red[k]; out[b] = s + b2[0]; }
}

// ---------------------------------------------------------------------------
// Launch: reset -> gemm0 -> fused(rec0 || gemm1 || rec1) -> head
// ---------------------------------------------------------------------------
extern "C" void kernel_launch(void* const* d_in, const int* in_sizes, int n_in,
                              void* d_out, int out_size)
{
    const float* mapf = (const float*)d_in[0];
    const float* pos  = (const float*)d_in[1];
    const float* Wih0 = (const float*)d_in[2];
    const float* Whh0 = (const float*)d_in[3];
    const float* bih0 = (const float*)d_in[4];
    const float* bhh0 = (const float*)d_in[5];
    const float* Wih1 = (const float*)d_in[6];
    const float* Whh1 = (const float*)d_in[7];
    const float* bih1 = (const float*)d_in[8];
    const float* bhh1 = (const float*)d_in[9];
    const float* W1   = (const float*)d_in[10];
    const float* b1   = (const float*)d_in[11];
    const float* lng  = (const float*)d_in[12];
    const float* lnb  = (const float*)d_in[13];
    const float* W2   = (const float*)d_in[14];
    const float* b2   = (const float*)d_in[15];
    float* out = (float*)d_out;

    cudaFuncSetAttribute((const void*)xproj_gemm0,
                         cudaFuncAttributeMaxDynamicSharedMemorySize, GEMM4_SMEM);
    cudaFuncSetAttribute((const void*)fused_pipeline,
                         cudaFuncAttributeMaxDynamicSharedMemorySize, FUSED_SMEM);

    reset_flags<<<1, 1>>>();
    dim3 gg(T / 4, 8);
    xproj_gemm0<<<gg, 256, GEMM4_SMEM>>>(mapf, pos, Wih0, bih0, bhh0);
    fused_pipeline<<<RECC0 + NG + RECC1, 256, FUSED_SMEM>>>(
        Whh0, Wih1, bih1, bhh1, Whh1);
    head_kernel<<<B, 64>>>(W1, b1, lng, lnb, W2, b2, out);
}